// round 15
// baseline (speedup 1.0000x reference)
#include <cuda_runtime.h>
#include <cuda_fp16.h>
#include <cstdint>

// ----------------------------------------------------------------------------
// AdaAffcell, quad-group persistent kernel (sm_103 base ISA: HMMA mma.sync).
//   hx = [h, x] (B x 256); g = hx W_g^T + b_g ; z = hx W_a^T + b_a
//   h~ = sigmoid(g)*tanh(z) + (1-sigmoid(g))*z ; out = LN(h~)*gamma + beta
//
// R13 champion structure: 256 threads = 4 independent groups of 2 warps,
// group = 32-row tile, group-local 64-thread named barriers, warp = 32 rows x
// (64 g + 64 z cols) (128 acc regs). W (fp16 [256][264]) resident in SMEM.
// R15: epilogue transcendentals via tanh.approx.f16x2 (pairs packed in half2)
// -> MUFU instruction count halved (256 -> 128 per thread per tile); the
// gated mix and the z linear term stay in fp32.
// ----------------------------------------------------------------------------

#define NROWS  524288
#define GTILE  32
#define NT     (NROWS / GTILE)     // 16384
#define EPSV   1e-5f

__device__ __align__(16) __half g_Wimg[256 * 264];

// SMEM layout (bytes)
#define SMEM_W     0               // fp16 [256][264] = 135168
#define SMEM_A     135168          // 4 buffers of 32x264 fp16 = 16896 each
#define SMEM_BG    202752          // f32 [128]
#define SMEM_BA    203264
#define SMEM_GAM   203776
#define SMEM_BET   204288
#define SMEM_PS    204800          // float2 [4][32][2] = 2048
#define SMEM_TOTAL 206848

#define BAR_SYNC(id) asm volatile("bar.sync %0, 64;" :: "r"(id) : "memory")

static __device__ __forceinline__ uint32_t smem_u32(const void* p) {
    uint32_t a;
    asm("{ .reg .u64 t; cvta.to.shared.u64 t, %1; cvt.u32.u64 %0, t; }"
        : "=r"(a) : "l"(p));
    return a;
}

// Two tanh in one MUFU op via f16x2.
static __device__ __forceinline__ float2 tanh2_fast(float a, float b) {
    __half2 hin = __floats2half2_rn(a, b);
    uint32_t u = *reinterpret_cast<uint32_t*>(&hin);
    uint32_t r;
    asm("tanh.approx.f16x2 %0, %1;" : "=r"(r) : "r"(u));
    __half2 hout = *reinterpret_cast<__half2*>(&r);
    return __half22float2(hout);
}

#define LDSM4(r0, r1, r2, r3, addr)                                              \
    asm volatile("ldmatrix.sync.aligned.m8n8.x4.shared.b16 {%0,%1,%2,%3}, [%4];" \
                 : "=r"(r0), "=r"(r1), "=r"(r2), "=r"(r3) : "r"(addr))

#define MMA16816(c, a0, a1, a2, a3, b0, b1)                                  \
    asm volatile("mma.sync.aligned.m16n8k16.row.col.f32.f16.f16.f32 "        \
                 "{%0,%1,%2,%3}, {%4,%5,%6,%7}, {%8,%9}, {%0,%1,%2,%3};"     \
                 : "+f"((c)[0]), "+f"((c)[1]), "+f"((c)[2]), "+f"((c)[3])    \
                 : "r"(a0), "r"(a1), "r"(a2), "r"(a3), "r"(b0), "r"(b1))

// ---------------------------------------------------------------------------
__global__ void prep_w_kernel(const float* __restrict__ Wa, const float* __restrict__ Wg) {
    int i = blockIdx.x * 256 + threadIdx.x;   // 0..65535
    int n = i >> 8;
    int k = i & 255;
    float v = (n < 128) ? Wg[n * 256 + k] : Wa[(n - 128) * 256 + k];
    g_Wimg[n * 264 + k] = __float2half_rn(v);
}

// ---------------------------------------------------------------------------
__global__ void __launch_bounds__(256, 1) adaaff_kernel(
    const float* __restrict__ x, const float* __restrict__ h,
    const float* __restrict__ b_a, const float* __restrict__ b_g,
    const float* __restrict__ gamma, const float* __restrict__ beta,
    float* __restrict__ out)
{
    extern __shared__ __align__(16) char smem[];
    const uint32_t smem_base = smem_u32(smem);
    const int tid  = threadIdx.x;
    const int lane = tid & 31;
    const int wid  = tid >> 5;
    const int g    = wid >> 1;       // group 0..3
    const int wq   = wid & 1;        // warp within group (feature half)
    const int tig  = lane & 3;
    const int gq   = lane >> 2;
    const int barid = 1 + g;

    // ---- one-time setup: vectors + W tile ----
    if (tid < 128) {
        *(float*)(smem + SMEM_BG  + tid * 4) = b_g[tid];
        *(float*)(smem + SMEM_BA  + tid * 4) = b_a[tid];
        *(float*)(smem + SMEM_GAM + tid * 4) = gamma[tid];
        *(float*)(smem + SMEM_BET + tid * 4) = beta[tid];
    }
    {
        const uint4* src = (const uint4*)g_Wimg;
        uint4* dst = (uint4*)(smem + SMEM_W);
        for (int i = tid; i < 8448; i += 256) dst[i] = src[i];
    }

    // ---- staging: 64 threads/group, thread owns one float4 column slice ----
    const int  sc   = tid & 63;
    const bool s_h  = (sc < 32);
    const float* sbase = s_h ? (h + sc * 4) : (x + (sc - 32) * 4);
    const int  sk0  = s_h ? sc * 4 : 128 + (sc - 32) * 4;

    __half* sA = (__half*)(smem + SMEM_A + g * 16896);
    float4 st[8];

    // ---- prologue: fill this group's buffer with tile t (4 passes) ----
    int t = blockIdx.x * 4 + g;
    const int tstep = gridDim.x * 4;
    if (t < NT) {
        const size_t r0 = (size_t)t * GTILE;
        #pragma unroll
        for (int p = 0; p < 4; p++) {
            #pragma unroll
            for (int j = 0; j < 8; j++)
                st[j] = *(const float4*)&sbase[(r0 + (size_t)(8 * p + j)) * 128];
            #pragma unroll
            for (int j = 0; j < 8; j++) {
                const int m = 8 * p + j;
                __half2 p0 = __floats2half2_rn(st[j].x, st[j].y);
                __half2 p1 = __floats2half2_rn(st[j].z, st[j].w);
                *(uint2*)&sA[m * 264 + sk0] =
                    make_uint2(*(uint32_t*)&p0, *(uint32_t*)&p1);
            }
        }
    }
    __syncthreads();     // W + vectors + all prologue buffers visible

    // ---- ldmatrix lane addressing ----
    const uint32_t a_base = smem_base + SMEM_A + (uint32_t)g * 16896;
    uint32_t a_addr[2];
    #pragma unroll
    for (int i = 0; i < 2; i++) {
        int r  = 16 * i + (lane & 15);
        int kq = (lane >> 4) * 8;
        a_addr[i] = a_base + (uint32_t)(r * 264 + kq) * 2;
    }
    // 8 B-fragment bases: j2 0..3 -> g cols wq*64 + 16*j2; j2 4..7 -> z (+128)
    uint32_t b_addr[8];
    #pragma unroll
    for (int j2 = 0; j2 < 8; j2++) {
        int nb = wq * 64 + (j2 & 3) * 16 + (j2 >> 2) * 128;
        int n  = nb + (lane & 7) + ((lane >> 4) & 1) * 8;
        int kq = ((lane >> 3) & 1) * 8;
        b_addr[j2] = smem_base + SMEM_W + (uint32_t)(n * 264 + kq) * 2;
    }

    float*  s_bg  = (float*)(smem + SMEM_BG);
    float*  s_ba  = (float*)(smem + SMEM_BA);
    float*  s_gam = (float*)(smem + SMEM_GAM);
    float*  s_bet = (float*)(smem + SMEM_BET);
    float2* s_ps  = (float2*)(smem + SMEM_PS) + g * 64;   // [32][2]

    const bool o1 = (tig & 1), o2 = (tig & 2);

    while (t < NT) {
        // ---- 1. MMA: warp = 32 rows x (64 g + 64 z cols), acc 128 ----
        float c[2][16][4];
        #pragma unroll
        for (int i = 0; i < 2; i++)
            #pragma unroll
            for (int j = 0; j < 16; j++)
                #pragma unroll
                for (int e = 0; e < 4; e++) c[i][j][e] = 0.0f;

        #pragma unroll
        for (int s = 0; s < 16; s++) {
            const uint32_t ko = (uint32_t)s * 32;
            uint32_t ar[2][4];
            #pragma unroll
            for (int i = 0; i < 2; i++)
                LDSM4(ar[i][0], ar[i][1], ar[i][2], ar[i][3], a_addr[i] + ko);
            #pragma unroll
            for (int j2 = 0; j2 < 8; j2++) {
                uint32_t b0, b1, b2, b3;
                LDSM4(b0, b1, b2, b3, b_addr[j2] + ko);
                #pragma unroll
                for (int i = 0; i < 2; i++) {
                    MMA16816(c[i][2 * j2],     ar[i][0], ar[i][1], ar[i][2], ar[i][3], b0, b1);
                    MMA16816(c[i][2 * j2 + 1], ar[i][0], ar[i][1], ar[i][2], ar[i][3], b2, b3);
                }
            }
        }

        // ---- 2. activation (f16x2 tanh pairs) + row partials ----
        float rsum[4] = {0.f, 0.f, 0.f, 0.f};
        float rsq[4]  = {0.f, 0.f, 0.f, 0.f};
        #pragma unroll
        for (int i = 0; i < 2; i++) {
            #pragma unroll
            for (int j = 0; j < 8; j++) {
                const int f0 = wq * 64 + j * 8 + 2 * tig;
                #pragma unroll
                for (int rh = 0; rh < 2; rh++) {
                    float gv0 = c[i][j][rh * 2 + 0]     + s_bg[f0];
                    float gv1 = c[i][j][rh * 2 + 1]     + s_bg[f0 + 1];
                    float zv0 = c[i][j + 8][rh * 2 + 0] + s_ba[f0];
                    float zv1 = c[i][j + 8][rh * 2 + 1] + s_ba[f0 + 1];
                    float2 tg = tanh2_fast(0.5f * gv0, 0.5f * gv1);
                    float2 tz = tanh2_fast(zv0, zv1);
                    float al0 = 0.5f + 0.5f * tg.x;
                    float al1 = 0.5f + 0.5f * tg.y;
                    float ht0 = al0 * tz.x + (1.0f - al0) * zv0;
                    float ht1 = al1 * tz.y + (1.0f - al1) * zv1;
                    c[i][j][rh * 2 + 0] = ht0;
                    c[i][j][rh * 2 + 1] = ht1;
                    rsum[i * 2 + rh] += ht0 + ht1;
                    rsq[i * 2 + rh]  += ht0 * ht0 + ht1 * ht1;
                }
            }
        }
        #pragma unroll
        for (int r = 0; r < 4; r++) {
            float sv = rsum[r], qv = rsq[r];
            sv += __shfl_xor_sync(0xffffffffu, sv, 1);
            qv += __shfl_xor_sync(0xffffffffu, qv, 1);
            sv += __shfl_xor_sync(0xffffffffu, sv, 2);
            qv += __shfl_xor_sync(0xffffffffu, qv, 2);
            if (tig == 0) {
                const int rowl = 16 * (r >> 1) + 8 * (r & 1) + gq;
                s_ps[rowl * 2 + wq] = make_float2(sv, qv);
            }
        }

        // ---- 3. prefetch LDG pass0 for tile t+step ----
        const int nt = t + tstep;
        const bool has_next = (nt < NT);
        const size_t r0n = (size_t)nt * GTILE;
        if (has_next) {
            #pragma unroll
            for (int j = 0; j < 8; j++)
                st[j] = *(const float4*)&sbase[(r0n + (size_t)j) * 128];
        }
        BAR_SYNC(barid);               // psum ready; all MMA reads of buffer done

        // ---- 4. STS pass0, issue LDG pass1 (covered by norm/STG below) ----
        if (has_next) {
            #pragma unroll
            for (int j = 0; j < 8; j++) {
                __half2 p0 = __floats2half2_rn(st[j].x, st[j].y);
                __half2 p1 = __floats2half2_rn(st[j].z, st[j].w);
                *(uint2*)&sA[j * 264 + sk0] =
                    make_uint2(*(uint32_t*)&p0, *(uint32_t*)&p1);
            }
            #pragma unroll
            for (int j = 0; j < 8; j++)
                st[j] = *(const float4*)&sbase[(r0n + (size_t)(8 + j)) * 128];
        }

        // ---- 5. normalize + quad-transpose + coalesced STG.128 ----
        {
            const size_t r0 = (size_t)t * GTILE;
            #pragma unroll
            for (int i = 0; i < 2; i++) {
                #pragma unroll
                for (int rh = 0; rh < 2; rh++) {
                    const int rowl = 16 * i + 8 * rh + gq;
                    float2 p0v = s_ps[rowl * 2];
                    float2 p1v = s_ps[rowl * 2 + 1];
                    const float sv = p0v.x + p1v.x;
                    const float qv = p0v.y + p1v.y;
                    const float mu = sv * (1.0f / 128.0f);
                    const float rs = rsqrtf(qv * (1.0f / 128.0f) - mu * mu + EPSV);
                    const size_t gr = r0 + (size_t)rowl;

                    #pragma unroll
                    for (int blk = 0; blk < 2; blk++) {
                        float F[8];
                        #pragma unroll
                        for (int jj = 0; jj < 4; jj++) {
                            F[2 * jj]     = (c[i][4 * blk + jj][rh * 2 + 0] - mu) * rs;
                            F[2 * jj + 1] = (c[i][4 * blk + jj][rh * 2 + 1] - mu) * rs;
                        }
                        // 4x4 quad transpose (float2 entries), butterfly xor1/xor2
                        {
                            float sa0 = o1 ? F[0] : F[2], sa1 = o1 ? F[1] : F[3];
                            float sb0 = o1 ? F[4] : F[6], sb1 = o1 ? F[5] : F[7];
                            float ra0 = __shfl_xor_sync(0xffffffffu, sa0, 1);
                            float ra1 = __shfl_xor_sync(0xffffffffu, sa1, 1);
                            float rb0 = __shfl_xor_sync(0xffffffffu, sb0, 1);
                            float rb1 = __shfl_xor_sync(0xffffffffu, sb1, 1);
                            F[0] = o1 ? ra0 : F[0];  F[1] = o1 ? ra1 : F[1];
                            F[2] = o1 ? F[2] : ra0;  F[3] = o1 ? F[3] : ra1;
                            F[4] = o1 ? rb0 : F[4];  F[5] = o1 ? rb1 : F[5];
                            F[6] = o1 ? F[6] : rb0;  F[7] = o1 ? F[7] : rb1;

                            sa0 = o2 ? F[0] : F[4];  sa1 = o2 ? F[1] : F[5];
                            sb0 = o2 ? F[2] : F[6];  sb1 = o2 ? F[3] : F[7];
                            ra0 = __shfl_xor_sync(0xffffffffu, sa0, 2);
                            ra1 = __shfl_xor_sync(0xffffffffu, sa1, 2);
                            rb0 = __shfl_xor_sync(0xffffffffu, sb0, 2);
                            rb1 = __shfl_xor_sync(0xffffffffu, sb1, 2);
                            F[0] = o2 ? ra0 : F[0];  F[1] = o2 ? ra1 : F[1];
                            F[4] = o2 ? F[4] : ra0;  F[5] = o2 ? F[5] : ra1;
                            F[2] = o2 ? rb0 : F[2];  F[3] = o2 ? rb1 : F[3];
                            F[6] = o2 ? F[6] : rb0;  F[7] = o2 ? F[7] : rb1;
                        }
                        const int fb = wq * 64 + 32 * blk + tig * 8;
                        float4 gm0 = *(const float4*)&s_gam[fb];
                        float4 gm1 = *(const float4*)&s_gam[fb + 4];
                        float4 bt0 = *(const float4*)&s_bet[fb];
                        float4 bt1 = *(const float4*)&s_bet[fb + 4];
                        float4 v0 = make_float4(F[0] * gm0.x + bt0.x, F[1] * gm0.y + bt0.y,
                                                F[2] * gm0.z + bt0.z, F[3] * gm0.w + bt0.w);
                        float4 v1 = make_float4(F[4] * gm1.x + bt1.x, F[5] * gm1.y + bt1.y,
                                                F[6] * gm1.z + bt1.z, F[7] * gm1.w + bt1.w);
                        *(float4*)&out[gr * 128 + fb]     = v0;
                        *(float4*)&out[gr * 128 + fb + 4] = v1;
                    }
                }
            }
        }

        // ---- 6. remaining refill: STS1, LDG2, STS2, LDG3, STS3 ----
        if (has_next) {
            #pragma unroll
            for (int j = 0; j < 8; j++) {
                const int m = 8 + j;
                __half2 p0 = __floats2half2_rn(st[j].x, st[j].y);
                __half2 p1 = __floats2half2_rn(st[j].z, st[j].w);
                *(uint2*)&sA[m * 264 + sk0] =
                    make_uint2(*(uint32_t*)&p0, *(uint32_t*)&p1);
            }
            #pragma unroll
            for (int p = 2; p < 4; p++) {
                #pragma unroll
                for (int j = 0; j < 8; j++)
                    st[j] = *(const float4*)&sbase[(r0n + (size_t)(8 * p + j)) * 128];
                #pragma unroll
                for (int j = 0; j < 8; j++) {
                    const int m = 8 * p + j;
                    __half2 p0 = __floats2half2_rn(st[j].x, st[j].y);
                    __half2 p1 = __floats2half2_rn(st[j].z, st[j].w);
                    *(uint2*)&sA[m * 264 + sk0] =
                        make_uint2(*(uint32_t*)&p0, *(uint32_t*)&p1);
                }
            }
        }
        BAR_SYNC(barid);               // buffer refilled; psum reads done

        t = nt;
    }
}

// ---------------------------------------------------------------------------
extern "C" void kernel_launch(void* const* d_in, const int* in_sizes, int n_in,
                              void* d_out, int out_size) {
    const float* x     = (const float*)d_in[0];
    const float* h     = (const float*)d_in[1];
    const float* W_a   = (const float*)d_in[2];
    const float* W_g   = (const float*)d_in[3];
    const float* b_a   = (const float*)d_in[4];
    const float* b_g   = (const float*)d_in[5];
    const float* gamma = (const float*)d_in[6];
    const float* beta  = (const float*)d_in[7];
    float* out = (float*)d_out;

    static int nsm = 0;
    if (nsm == 0) {
        int dev = 0, v = 0;
        nsm = 148;
        if (cudaGetDevice(&dev) == cudaSuccess &&
            cudaDeviceGetAttribute(&v, cudaDevAttrMultiProcessorCount, dev) == cudaSuccess &&
            v > 0)
            nsm = v;
        cudaFuncSetAttribute(adaaff_kernel,
                             cudaFuncAttributeMaxDynamicSharedMemorySize, SMEM_TOTAL);
    }

    prep_w_kernel<<<256, 256>>>(W_a, W_g);
    adaaff_kernel<<<nsm, 256, SMEM_TOTAL>>>(x, h, b_a, b_g, gamma, beta, out);
}

// round 16
// speedup vs baseline: 1.4121x; 1.4121x over previous
#include <cuda_runtime.h>
#include <cuda_fp16.h>
#include <cstdint>

// ----------------------------------------------------------------------------
// AdaAffcell, quad-group persistent kernel (sm_103 base ISA: HMMA mma.sync).
//   hx = [h, x] (B x 256); g = hx W_g^T + b_g ; z = hx W_a^T + b_a
//   h~ = sigmoid(g)*tanh(z) + (1-sigmoid(g))*z ; out = LN(h~)*gamma + beta
//
// R13 champion structure: 256 threads = 4 independent groups of 2 warps,
// group = 32-row tile, group-local 64-thread named barriers, warp = 32 rows x
// (64 g + 64 z cols) (128 acc regs). W (fp16 [256][264]) resident in SMEM.
// R16: refill interleaved with the two norm/STG halves so LDG1/LDG2 latency
// is covered by epilogue work (only LDG3 partially exposed); output stores
// use __stcs (evict-first) to keep L2 clean for the input stream.
// ----------------------------------------------------------------------------

#define NROWS  524288
#define GTILE  32
#define NT     (NROWS / GTILE)     // 16384
#define EPSV   1e-5f

__device__ __align__(16) __half g_Wimg[256 * 264];

// SMEM layout (bytes)
#define SMEM_W     0               // fp16 [256][264] = 135168
#define SMEM_A     135168          // 4 buffers of 32x264 fp16 = 16896 each
#define SMEM_BG    202752          // f32 [128]
#define SMEM_BA    203264
#define SMEM_GAM   203776
#define SMEM_BET   204288
#define SMEM_PS    204800          // float2 [4][32][2] = 2048
#define SMEM_TOTAL 206848

#define BAR_SYNC(id) asm volatile("bar.sync %0, 64;" :: "r"(id) : "memory")

static __device__ __forceinline__ uint32_t smem_u32(const void* p) {
    uint32_t a;
    asm("{ .reg .u64 t; cvta.to.shared.u64 t, %1; cvt.u32.u64 %0, t; }"
        : "=r"(a) : "l"(p));
    return a;
}

static __device__ __forceinline__ float tanh_fast(float v) {
    float r;
    asm("tanh.approx.f32 %0, %1;" : "=f"(r) : "f"(v));
    return r;
}

#define LDSM4(r0, r1, r2, r3, addr)                                              \
    asm volatile("ldmatrix.sync.aligned.m8n8.x4.shared.b16 {%0,%1,%2,%3}, [%4];" \
                 : "=r"(r0), "=r"(r1), "=r"(r2), "=r"(r3) : "r"(addr))

#define MMA16816(c, a0, a1, a2, a3, b0, b1)                                  \
    asm volatile("mma.sync.aligned.m16n8k16.row.col.f32.f16.f16.f32 "        \
                 "{%0,%1,%2,%3}, {%4,%5,%6,%7}, {%8,%9}, {%0,%1,%2,%3};"     \
                 : "+f"((c)[0]), "+f"((c)[1]), "+f"((c)[2]), "+f"((c)[3])    \
                 : "r"(a0), "r"(a1), "r"(a2), "r"(a3), "r"(b0), "r"(b1))

// ---------------------------------------------------------------------------
__global__ void prep_w_kernel(const float* __restrict__ Wa, const float* __restrict__ Wg) {
    int i = blockIdx.x * 256 + threadIdx.x;   // 0..65535
    int n = i >> 8;
    int k = i & 255;
    float v = (n < 128) ? Wg[n * 256 + k] : Wa[(n - 128) * 256 + k];
    g_Wimg[n * 264 + k] = __float2half_rn(v);
}

// ---------------------------------------------------------------------------
__global__ void __launch_bounds__(256, 1) adaaff_kernel(
    const float* __restrict__ x, const float* __restrict__ h,
    const float* __restrict__ b_a, const float* __restrict__ b_g,
    const float* __restrict__ gamma, const float* __restrict__ beta,
    float* __restrict__ out)
{
    extern __shared__ __align__(16) char smem[];
    const uint32_t smem_base = smem_u32(smem);
    const int tid  = threadIdx.x;
    const int lane = tid & 31;
    const int wid  = tid >> 5;
    const int g    = wid >> 1;       // group 0..3
    const int wq   = wid & 1;        // warp within group (feature half)
    const int tig  = lane & 3;
    const int gq   = lane >> 2;
    const int barid = 1 + g;

    // ---- one-time setup: vectors + W tile ----
    if (tid < 128) {
        *(float*)(smem + SMEM_BG  + tid * 4) = b_g[tid];
        *(float*)(smem + SMEM_BA  + tid * 4) = b_a[tid];
        *(float*)(smem + SMEM_GAM + tid * 4) = gamma[tid];
        *(float*)(smem + SMEM_BET + tid * 4) = beta[tid];
    }
    {
        const uint4* src = (const uint4*)g_Wimg;
        uint4* dst = (uint4*)(smem + SMEM_W);
        for (int i = tid; i < 8448; i += 256) dst[i] = src[i];
    }

    // ---- staging: 64 threads/group, thread owns one float4 column slice ----
    const int  sc   = tid & 63;
    const bool s_h  = (sc < 32);
    const float* sbase = s_h ? (h + sc * 4) : (x + (sc - 32) * 4);
    const int  sk0  = s_h ? sc * 4 : 128 + (sc - 32) * 4;

    __half* sA = (__half*)(smem + SMEM_A + g * 16896);
    float4 st[8];

    // ---- prologue: fill this group's buffer with tile t (4 passes) ----
    int t = blockIdx.x * 4 + g;
    const int tstep = gridDim.x * 4;
    if (t < NT) {
        const size_t r0 = (size_t)t * GTILE;
        #pragma unroll
        for (int p = 0; p < 4; p++) {
            #pragma unroll
            for (int j = 0; j < 8; j++)
                st[j] = *(const float4*)&sbase[(r0 + (size_t)(8 * p + j)) * 128];
            #pragma unroll
            for (int j = 0; j < 8; j++) {
                const int m = 8 * p + j;
                __half2 p0 = __floats2half2_rn(st[j].x, st[j].y);
                __half2 p1 = __floats2half2_rn(st[j].z, st[j].w);
                *(uint2*)&sA[m * 264 + sk0] =
                    make_uint2(*(uint32_t*)&p0, *(uint32_t*)&p1);
            }
        }
    }
    __syncthreads();     // W + vectors + all prologue buffers visible

    // ---- ldmatrix lane addressing ----
    const uint32_t a_base = smem_base + SMEM_A + (uint32_t)g * 16896;
    uint32_t a_addr[2];
    #pragma unroll
    for (int i = 0; i < 2; i++) {
        int r  = 16 * i + (lane & 15);
        int kq = (lane >> 4) * 8;
        a_addr[i] = a_base + (uint32_t)(r * 264 + kq) * 2;
    }
    // 8 B-fragment bases: j2 0..3 -> g cols wq*64 + 16*j2; j2 4..7 -> z (+128)
    uint32_t b_addr[8];
    #pragma unroll
    for (int j2 = 0; j2 < 8; j2++) {
        int nb = wq * 64 + (j2 & 3) * 16 + (j2 >> 2) * 128;
        int n  = nb + (lane & 7) + ((lane >> 4) & 1) * 8;
        int kq = ((lane >> 3) & 1) * 8;
        b_addr[j2] = smem_base + SMEM_W + (uint32_t)(n * 264 + kq) * 2;
    }

    float*  s_bg  = (float*)(smem + SMEM_BG);
    float*  s_ba  = (float*)(smem + SMEM_BA);
    float*  s_gam = (float*)(smem + SMEM_GAM);
    float*  s_bet = (float*)(smem + SMEM_BET);
    float2* s_ps  = (float2*)(smem + SMEM_PS) + g * 64;   // [32][2]

    const bool o1 = (tig & 1), o2 = (tig & 2);

    while (t < NT) {
        // ---- 1. MMA: warp = 32 rows x (64 g + 64 z cols), acc 128 ----
        float c[2][16][4];
        #pragma unroll
        for (int i = 0; i < 2; i++)
            #pragma unroll
            for (int j = 0; j < 16; j++)
                #pragma unroll
                for (int e = 0; e < 4; e++) c[i][j][e] = 0.0f;

        #pragma unroll
        for (int s = 0; s < 16; s++) {
            const uint32_t ko = (uint32_t)s * 32;
            uint32_t ar[2][4];
            #pragma unroll
            for (int i = 0; i < 2; i++)
                LDSM4(ar[i][0], ar[i][1], ar[i][2], ar[i][3], a_addr[i] + ko);
            #pragma unroll
            for (int j2 = 0; j2 < 8; j2++) {
                uint32_t b0, b1, b2, b3;
                LDSM4(b0, b1, b2, b3, b_addr[j2] + ko);
                #pragma unroll
                for (int i = 0; i < 2; i++) {
                    MMA16816(c[i][2 * j2],     ar[i][0], ar[i][1], ar[i][2], ar[i][3], b0, b1);
                    MMA16816(c[i][2 * j2 + 1], ar[i][0], ar[i][1], ar[i][2], ar[i][3], b2, b3);
                }
            }
        }

        // ---- 2. activation + row partials ----
        float rsum[4] = {0.f, 0.f, 0.f, 0.f};
        float rsq[4]  = {0.f, 0.f, 0.f, 0.f};
        #pragma unroll
        for (int i = 0; i < 2; i++) {
            #pragma unroll
            for (int j = 0; j < 8; j++) {
                const int f0 = wq * 64 + j * 8 + 2 * tig;
                #pragma unroll
                for (int rh = 0; rh < 2; rh++) {
                    #pragma unroll
                    for (int e = 0; e < 2; e++) {
                        const int f = f0 + e;
                        float gv = c[i][j][rh * 2 + e] + s_bg[f];
                        float zv = c[i][j + 8][rh * 2 + e] + s_ba[f];
                        float al = 0.5f + 0.5f * tanh_fast(0.5f * gv);   // sigmoid
                        float ht = al * tanh_fast(zv) + (1.0f - al) * zv;
                        c[i][j][rh * 2 + e] = ht;
                        rsum[i * 2 + rh] += ht;
                        rsq[i * 2 + rh]  += ht * ht;
                    }
                }
            }
        }
        #pragma unroll
        for (int r = 0; r < 4; r++) {
            float sv = rsum[r], qv = rsq[r];
            sv += __shfl_xor_sync(0xffffffffu, sv, 1);
            qv += __shfl_xor_sync(0xffffffffu, qv, 1);
            sv += __shfl_xor_sync(0xffffffffu, sv, 2);
            qv += __shfl_xor_sync(0xffffffffu, qv, 2);
            if (tig == 0) {
                const int rowl = 16 * (r >> 1) + 8 * (r & 1) + gq;
                s_ps[rowl * 2 + wq] = make_float2(sv, qv);
            }
        }

        // ---- 3. prefetch LDG pass0 for tile t+step ----
        const int nt = t + tstep;
        const bool has_next = (nt < NT);
        const size_t r0n = (size_t)nt * GTILE;
        if (has_next) {
            #pragma unroll
            for (int j = 0; j < 8; j++)
                st[j] = *(const float4*)&sbase[(r0n + (size_t)j) * 128];
        }
        BAR_SYNC(barid);               // psum ready; all MMA reads of buffer done

        // ---- 4. STS pass0, issue LDG pass1 ----
        if (has_next) {
            #pragma unroll
            for (int j = 0; j < 8; j++) {
                __half2 p0 = __floats2half2_rn(st[j].x, st[j].y);
                __half2 p1 = __floats2half2_rn(st[j].z, st[j].w);
                *(uint2*)&sA[j * 264 + sk0] =
                    make_uint2(*(uint32_t*)&p0, *(uint32_t*)&p1);
            }
            #pragma unroll
            for (int j = 0; j < 8; j++)
                st[j] = *(const float4*)&sbase[(r0n + (size_t)(8 + j)) * 128];
        }

        // ---- 5. normalize + quad-transpose + __stcs, refill interleaved ----
        {
            const size_t r0 = (size_t)t * GTILE;
            #pragma unroll
            for (int i = 0; i < 2; i++) {
                #pragma unroll
                for (int rh = 0; rh < 2; rh++) {
                    const int rowl = 16 * i + 8 * rh + gq;
                    float2 p0v = s_ps[rowl * 2];
                    float2 p1v = s_ps[rowl * 2 + 1];
                    const float sv = p0v.x + p1v.x;
                    const float qv = p0v.y + p1v.y;
                    const float mu = sv * (1.0f / 128.0f);
                    const float rs = rsqrtf(qv * (1.0f / 128.0f) - mu * mu + EPSV);
                    const size_t gr = r0 + (size_t)rowl;

                    #pragma unroll
                    for (int blk = 0; blk < 2; blk++) {
                        float F[8];
                        #pragma unroll
                        for (int jj = 0; jj < 4; jj++) {
                            F[2 * jj]     = (c[i][4 * blk + jj][rh * 2 + 0] - mu) * rs;
                            F[2 * jj + 1] = (c[i][4 * blk + jj][rh * 2 + 1] - mu) * rs;
                        }
                        // 4x4 quad transpose (float2 entries), butterfly xor1/xor2
                        {
                            float sa0 = o1 ? F[0] : F[2], sa1 = o1 ? F[1] : F[3];
                            float sb0 = o1 ? F[4] : F[6], sb1 = o1 ? F[5] : F[7];
                            float ra0 = __shfl_xor_sync(0xffffffffu, sa0, 1);
                            float ra1 = __shfl_xor_sync(0xffffffffu, sa1, 1);
                            float rb0 = __shfl_xor_sync(0xffffffffu, sb0, 1);
                            float rb1 = __shfl_xor_sync(0xffffffffu, sb1, 1);
                            F[0] = o1 ? ra0 : F[0];  F[1] = o1 ? ra1 : F[1];
                            F[2] = o1 ? F[2] : ra0;  F[3] = o1 ? F[3] : ra1;
                            F[4] = o1 ? rb0 : F[4];  F[5] = o1 ? rb1 : F[5];
                            F[6] = o1 ? F[6] : rb0;  F[7] = o1 ? F[7] : rb1;

                            sa0 = o2 ? F[0] : F[4];  sa1 = o2 ? F[1] : F[5];
                            sb0 = o2 ? F[2] : F[6];  sb1 = o2 ? F[3] : F[7];
                            ra0 = __shfl_xor_sync(0xffffffffu, sa0, 2);
                            ra1 = __shfl_xor_sync(0xffffffffu, sa1, 2);
                            rb0 = __shfl_xor_sync(0xffffffffu, sb0, 2);
                            rb1 = __shfl_xor_sync(0xffffffffu, sb1, 2);
                            F[0] = o2 ? ra0 : F[0];  F[1] = o2 ? ra1 : F[1];
                            F[4] = o2 ? F[4] : ra0;  F[5] = o2 ? F[5] : ra1;
                            F[2] = o2 ? rb0 : F[2];  F[3] = o2 ? rb1 : F[3];
                            F[6] = o2 ? F[6] : rb0;  F[7] = o2 ? F[7] : rb1;
                        }
                        const int fb = wq * 64 + 32 * blk + tig * 8;
                        float4 gm0 = *(const float4*)&s_gam[fb];
                        float4 gm1 = *(const float4*)&s_gam[fb + 4];
                        float4 bt0 = *(const float4*)&s_bet[fb];
                        float4 bt1 = *(const float4*)&s_bet[fb + 4];
                        float4 v0 = make_float4(F[0] * gm0.x + bt0.x, F[1] * gm0.y + bt0.y,
                                                F[2] * gm0.z + bt0.z, F[3] * gm0.w + bt0.w);
                        float4 v1 = make_float4(F[4] * gm1.x + bt1.x, F[5] * gm1.y + bt1.y,
                                                F[6] * gm1.z + bt1.z, F[7] * gm1.w + bt1.w);
                        __stcs((float4*)&out[gr * 128 + fb],     v0);
                        __stcs((float4*)&out[gr * 128 + fb + 4], v1);
                    }
                }
                // refill woven between the two norm halves:
                // end of i=0: STS pass1 + LDG pass2 (covered by norm i=1)
                // end of i=1: STS pass2 + LDG pass3
                if (has_next) {
                    const int mp = (i == 0) ? 8 : 16;     // rows of the STS pass
                    #pragma unroll
                    for (int j = 0; j < 8; j++) {
                        const int m = mp + j;
                        __half2 p0 = __floats2half2_rn(st[j].x, st[j].y);
                        __half2 p1 = __floats2half2_rn(st[j].z, st[j].w);
                        *(uint2*)&sA[m * 264 + sk0] =
                            make_uint2(*(uint32_t*)&p0, *(uint32_t*)&p1);
                    }
                    const int lp = (i == 0) ? 16 : 24;    // rows of the next LDG pass
                    #pragma unroll
                    for (int j = 0; j < 8; j++)
                        st[j] = *(const float4*)&sbase[(r0n + (size_t)(lp + j)) * 128];
                }
            }
        }

        // ---- 6. final STS pass3 ----
        if (has_next) {
            #pragma unroll
            for (int j = 0; j < 8; j++) {
                const int m = 24 + j;
                __half2 p0 = __floats2half2_rn(st[j].x, st[j].y);
                __half2 p1 = __floats2half2_rn(st[j].z, st[j].w);
                *(uint2*)&sA[m * 264 + sk0] =
                    make_uint2(*(uint32_t*)&p0, *(uint32_t*)&p1);
            }
        }
        BAR_SYNC(barid);               // buffer refilled; psum reads done

        t = nt;
    }
}

// ---------------------------------------------------------------------------
extern "C" void kernel_launch(void* const* d_in, const int* in_sizes, int n_in,
                              void* d_out, int out_size) {
    const float* x     = (const float*)d_in[0];
    const float* h     = (const float*)d_in[1];
    const float* W_a   = (const float*)d_in[2];
    const float* W_g   = (const float*)d_in[3];
    const float* b_a   = (const float*)d_in[4];
    const float* b_g   = (const float*)d_in[5];
    const float* gamma = (const float*)d_in[6];
    const float* beta  = (const float*)d_in[7];
    float* out = (float*)d_out;

    static int nsm = 0;
    if (nsm == 0) {
        int dev = 0, v = 0;
        nsm = 148;
        if (cudaGetDevice(&dev) == cudaSuccess &&
            cudaDeviceGetAttribute(&v, cudaDevAttrMultiProcessorCount, dev) == cudaSuccess &&
            v > 0)
            nsm = v;
        cudaFuncSetAttribute(adaaff_kernel,
                             cudaFuncAttributeMaxDynamicSharedMemorySize, SMEM_TOTAL);
    }

    prep_w_kernel<<<256, 256>>>(W_a, W_g);
    adaaff_kernel<<<nsm, 256, SMEM_TOTAL>>>(x, h, b_a, b_g, gamma, beta, out);
}